// round 1
// baseline (speedup 1.0000x reference)
#include <cuda_runtime.h>
#include <cuda_bf16.h>

// Scratch (no allocation allowed): per-class double sums, pixel counts, final means.
__device__ double             g_sums[3];
__device__ unsigned long long g_cnts[3];
__device__ float              g_means[3];

// ---------------------------------------------------------------------------
// Kernel 0: zero the accumulators (graph replays reuse them).
// ---------------------------------------------------------------------------
__global__ void iwap_zero_kernel() {
    int i = threadIdx.x;
    if (i < 3) {
        g_sums[i]  = 0.0;
        g_cnts[i]  = 0ull;
        g_means[i] = 0.0f;
    }
}

// ---------------------------------------------------------------------------
// Kernel 1: grid-stride reduction. Each work item = 4 pixels = 1 int4 of inst
// + 3 float4 of feats (48 contiguous bytes). Per-thread fp32 accumulation,
// block reduce in smem, one double/ull atomicAdd per class per block.
// ---------------------------------------------------------------------------
__global__ __launch_bounds__(256)
void iwap_reduce_kernel(const float4* __restrict__ feats4,
                        const int4*  __restrict__ inst4,
                        const float* __restrict__ feats,
                        const int*   __restrict__ inst,
                        int nitems, int npix) {
    float    s0 = 0.f, s1 = 0.f, s2 = 0.f;
    unsigned c0 = 0,   c1 = 0,   c2 = 0;

    const int stride = gridDim.x * blockDim.x;
    for (int i = blockIdx.x * blockDim.x + threadIdx.x; i < nitems; i += stride) {
        int4   cls = inst4[i];
        float4 a   = feats4[3 * i + 0];
        float4 b   = feats4[3 * i + 1];
        float4 d   = feats4[3 * i + 2];
        // pixel channel sums
        float p0 = a.x + a.y + a.z;
        float p1 = a.w + b.x + b.y;
        float p2 = b.z + b.w + d.x;
        float p3 = d.y + d.z + d.w;
        // branchless per-class accumulate
        s0 += (cls.x == 0) ? p0 : 0.f;  c0 += (cls.x == 0);
        s1 += (cls.x == 1) ? p0 : 0.f;  c1 += (cls.x == 1);
        s2 += (cls.x == 2) ? p0 : 0.f;  c2 += (cls.x == 2);
        s0 += (cls.y == 0) ? p1 : 0.f;  c0 += (cls.y == 0);
        s1 += (cls.y == 1) ? p1 : 0.f;  c1 += (cls.y == 1);
        s2 += (cls.y == 2) ? p1 : 0.f;  c2 += (cls.y == 2);
        s0 += (cls.z == 0) ? p2 : 0.f;  c0 += (cls.z == 0);
        s1 += (cls.z == 1) ? p2 : 0.f;  c1 += (cls.z == 1);
        s2 += (cls.z == 2) ? p2 : 0.f;  c2 += (cls.z == 2);
        s0 += (cls.w == 0) ? p3 : 0.f;  c0 += (cls.w == 0);
        s1 += (cls.w == 1) ? p3 : 0.f;  c1 += (cls.w == 1);
        s2 += (cls.w == 2) ? p3 : 0.f;  c2 += (cls.w == 2);
    }

    // Tail pixels (npix not divisible by 4) handled by thread 0 of block 0.
    if (blockIdx.x == 0 && threadIdx.x == 0) {
        for (int p = nitems * 4; p < npix; p++) {
            int   c  = inst[p];
            float ps = feats[3 * p] + feats[3 * p + 1] + feats[3 * p + 2];
            if      (c == 0) { s0 += ps; c0++; }
            else if (c == 1) { s1 += ps; c1++; }
            else if (c == 2) { s2 += ps; c2++; }
        }
    }

    // warp reduce
    #pragma unroll
    for (int off = 16; off > 0; off >>= 1) {
        s0 += __shfl_down_sync(0xffffffffu, s0, off);
        s1 += __shfl_down_sync(0xffffffffu, s1, off);
        s2 += __shfl_down_sync(0xffffffffu, s2, off);
        c0 += __shfl_down_sync(0xffffffffu, c0, off);
        c1 += __shfl_down_sync(0xffffffffu, c1, off);
        c2 += __shfl_down_sync(0xffffffffu, c2, off);
    }

    __shared__ float    bs[3];
    __shared__ unsigned bc[3];
    if (threadIdx.x < 3) { bs[threadIdx.x] = 0.f; bc[threadIdx.x] = 0u; }
    __syncthreads();
    if ((threadIdx.x & 31) == 0) {
        atomicAdd(&bs[0], s0); atomicAdd(&bs[1], s1); atomicAdd(&bs[2], s2);
        atomicAdd(&bc[0], c0); atomicAdd(&bc[1], c1); atomicAdd(&bc[2], c2);
    }
    __syncthreads();
    if (threadIdx.x < 3) {
        atomicAdd(&g_sums[threadIdx.x], (double)bs[threadIdx.x]);
        atomicAdd(&g_cnts[threadIdx.x], (unsigned long long)bc[threadIdx.x]);
    }
}

// ---------------------------------------------------------------------------
// Kernel 2: finalize means. count includes the 3 channels (x3).
// ---------------------------------------------------------------------------
__global__ void iwap_finalize_kernel() {
    int c = threadIdx.x;
    if (c < 3) {
        double cnt = 3.0 * (double)g_cnts[c];
        g_means[c] = (cnt > 0.0) ? (float)(g_sums[c] / cnt) : 0.0f;
    }
}

// ---------------------------------------------------------------------------
// Kernel 3: scatter. out[p, :] = means[inst[p]]. Fast path never touches
// feats; fallback copies original values for any out-of-range class.
// ---------------------------------------------------------------------------
__global__ __launch_bounds__(256)
void iwap_scatter_kernel(const int4*  __restrict__ inst4,
                         const float4* __restrict__ feats4,
                         float4* __restrict__ out4,
                         const int*   __restrict__ inst,
                         const float* __restrict__ feats,
                         float* __restrict__ out,
                         int nitems, int npix) {
    int i = blockIdx.x * blockDim.x + threadIdx.x;

    float m0 = g_means[0], m1 = g_means[1], m2 = g_means[2];

    if (i < nitems) {
        int4 cls = inst4[i];
        bool ok = ((unsigned)cls.x < 3u) & ((unsigned)cls.y < 3u) &
                  ((unsigned)cls.z < 3u) & ((unsigned)cls.w < 3u);
        if (ok) {
            float mp0 = (cls.x == 0) ? m0 : ((cls.x == 1) ? m1 : m2);
            float mp1 = (cls.y == 0) ? m0 : ((cls.y == 1) ? m1 : m2);
            float mp2 = (cls.z == 0) ? m0 : ((cls.z == 1) ? m1 : m2);
            float mp3 = (cls.w == 0) ? m0 : ((cls.w == 1) ? m1 : m2);
            out4[3 * i + 0] = make_float4(mp0, mp0, mp0, mp1);
            out4[3 * i + 1] = make_float4(mp1, mp1, mp2, mp2);
            out4[3 * i + 2] = make_float4(mp2, mp3, mp3, mp3);
        } else {
            // rare/impossible path: per-pixel scalar handling
            int cs[4] = {cls.x, cls.y, cls.z, cls.w};
            for (int q = 0; q < 4; q++) {
                int p = 4 * i + q;
                int c = cs[q];
                if ((unsigned)c < 3u) {
                    float m = (c == 0) ? m0 : ((c == 1) ? m1 : m2);
                    out[3 * p] = m; out[3 * p + 1] = m; out[3 * p + 2] = m;
                } else {
                    out[3 * p]     = feats[3 * p];
                    out[3 * p + 1] = feats[3 * p + 1];
                    out[3 * p + 2] = feats[3 * p + 2];
                }
            }
        }
    }

    // Tail pixels
    if (blockIdx.x == 0 && threadIdx.x == 0) {
        for (int p = nitems * 4; p < npix; p++) {
            int c = inst[p];
            if ((unsigned)c < 3u) {
                float m = (c == 0) ? m0 : ((c == 1) ? m1 : m2);
                out[3 * p] = m; out[3 * p + 1] = m; out[3 * p + 2] = m;
            } else {
                out[3 * p]     = feats[3 * p];
                out[3 * p + 1] = feats[3 * p + 1];
                out[3 * p + 2] = feats[3 * p + 2];
            }
        }
    }
}

// ---------------------------------------------------------------------------
extern "C" void kernel_launch(void* const* d_in, const int* in_sizes, int n_in,
                              void* d_out, int out_size) {
    const float* feats = (const float*)d_in[0];   // [16,1024,1024,3] f32
    const int*   inst  = (const int*)d_in[1];     // [16,1024,1024,1] i32
    float*       out   = (float*)d_out;

    const int npix   = in_sizes[1];               // 16*1024*1024
    const int nitems = npix >> 2;                 // 4 pixels per work item

    const float4* feats4 = (const float4*)feats;
    const int4*   inst4  = (const int4*)inst;
    float4*       out4   = (float4*)out;

    iwap_zero_kernel<<<1, 32>>>();

    // Grid-stride reduce: 8 blocks per SM keeps atomic count tiny while
    // saturating HBM.
    const int rblocks = 1216;  // ~8 * 152 SMs
    iwap_reduce_kernel<<<rblocks, 256>>>(feats4, inst4, feats, inst, nitems, npix);

    iwap_finalize_kernel<<<1, 32>>>();

    const int sblocks = (nitems + 255) / 256;
    iwap_scatter_kernel<<<sblocks, 256>>>(inst4, feats4, out4, inst, feats, out,
                                          nitems, npix);
}

// round 2
// speedup vs baseline: 1.1248x; 1.1248x over previous
#include <cuda_runtime.h>
#include <cuda_bf16.h>

// Scratch (no allocation allowed).
__device__ double             g_sums[3];
__device__ unsigned long long g_cnts[3];
__device__ float              g_means[3];

// ---------------------------------------------------------------------------
// Kernel 0: zero the accumulators (graph replays reuse them).
// ---------------------------------------------------------------------------
__global__ void iwap_zero_kernel() {
    int i = threadIdx.x;
    if (i < 3) {
        g_sums[i]  = 0.0;
        g_cnts[i]  = 0ull;
        g_means[i] = 0.0f;
    }
}

// ---------------------------------------------------------------------------
// Kernel 1: grid-stride reduction. 4 pixels per item = 1 int4 + 3 float4.
// feats is read with streaming (evict-first) hint so the inst lines survive
// in L2 for the scatter kernel. fp32 per-thread accumulation, double atomics
// once per block per class.
// ---------------------------------------------------------------------------
__global__ __launch_bounds__(256)
void iwap_reduce_kernel(const float4* __restrict__ feats4,
                        const int4*  __restrict__ inst4,
                        const float* __restrict__ feats,
                        const int*   __restrict__ inst,
                        int nitems, int npix) {
    float    s0 = 0.f, s1 = 0.f, s2 = 0.f;
    unsigned c0 = 0,   c1 = 0,   c2 = 0;

    const int stride = gridDim.x * blockDim.x;
    for (int i = blockIdx.x * blockDim.x + threadIdx.x; i < nitems; i += stride) {
        int4   cls = __ldg(&inst4[i]);               // keep in L2 (default policy)
        float4 a   = __ldcs(&feats4[3 * i + 0]);     // streaming: evict-first
        float4 b   = __ldcs(&feats4[3 * i + 1]);
        float4 d   = __ldcs(&feats4[3 * i + 2]);
        float p0 = a.x + a.y + a.z;
        float p1 = a.w + b.x + b.y;
        float p2 = b.z + b.w + d.x;
        float p3 = d.y + d.z + d.w;
        s0 += (cls.x == 0) ? p0 : 0.f;  c0 += (cls.x == 0);
        s1 += (cls.x == 1) ? p0 : 0.f;  c1 += (cls.x == 1);
        s2 += (cls.x == 2) ? p0 : 0.f;  c2 += (cls.x == 2);
        s0 += (cls.y == 0) ? p1 : 0.f;  c0 += (cls.y == 0);
        s1 += (cls.y == 1) ? p1 : 0.f;  c1 += (cls.y == 1);
        s2 += (cls.y == 2) ? p1 : 0.f;  c2 += (cls.y == 2);
        s0 += (cls.z == 0) ? p2 : 0.f;  c0 += (cls.z == 0);
        s1 += (cls.z == 1) ? p2 : 0.f;  c1 += (cls.z == 1);
        s2 += (cls.z == 2) ? p2 : 0.f;  c2 += (cls.z == 2);
        s0 += (cls.w == 0) ? p3 : 0.f;  c0 += (cls.w == 0);
        s1 += (cls.w == 1) ? p3 : 0.f;  c1 += (cls.w == 1);
        s2 += (cls.w == 2) ? p3 : 0.f;  c2 += (cls.w == 2);
    }

    // Tail pixels (npix not divisible by 4).
    if (blockIdx.x == 0 && threadIdx.x == 0) {
        for (int p = nitems * 4; p < npix; p++) {
            int   c  = inst[p];
            float ps = feats[3 * p] + feats[3 * p + 1] + feats[3 * p + 2];
            if      (c == 0) { s0 += ps; c0++; }
            else if (c == 1) { s1 += ps; c1++; }
            else if (c == 2) { s2 += ps; c2++; }
        }
    }

    #pragma unroll
    for (int off = 16; off > 0; off >>= 1) {
        s0 += __shfl_down_sync(0xffffffffu, s0, off);
        s1 += __shfl_down_sync(0xffffffffu, s1, off);
        s2 += __shfl_down_sync(0xffffffffu, s2, off);
        c0 += __shfl_down_sync(0xffffffffu, c0, off);
        c1 += __shfl_down_sync(0xffffffffu, c1, off);
        c2 += __shfl_down_sync(0xffffffffu, c2, off);
    }

    __shared__ float    bs[3];
    __shared__ unsigned bc[3];
    if (threadIdx.x < 3) { bs[threadIdx.x] = 0.f; bc[threadIdx.x] = 0u; }
    __syncthreads();
    if ((threadIdx.x & 31) == 0) {
        atomicAdd(&bs[0], s0); atomicAdd(&bs[1], s1); atomicAdd(&bs[2], s2);
        atomicAdd(&bc[0], c0); atomicAdd(&bc[1], c1); atomicAdd(&bc[2], c2);
    }
    __syncthreads();
    if (threadIdx.x < 3) {
        atomicAdd(&g_sums[threadIdx.x], (double)bs[threadIdx.x]);
        atomicAdd(&g_cnts[threadIdx.x], (unsigned long long)bc[threadIdx.x]);
    }
}

// ---------------------------------------------------------------------------
// Kernel 2: finalize means. Count includes the 3 channels (x3).
// ---------------------------------------------------------------------------
__global__ void iwap_finalize_kernel() {
    int c = threadIdx.x;
    if (c < 3) {
        double cnt = 3.0 * (double)g_cnts[c];
        g_means[c] = (cnt > 0.0) ? (float)(g_sums[c] / cnt) : 0.0f;
    }
}

// ---------------------------------------------------------------------------
// Kernel 3: scatter, smem-staged for perfectly coalesced writes.
// Each block handles a tile of 1024 pixels: 256 lane-contiguous int4 inst
// loads into smem, then 3*256 lane-contiguous float4 stores (each STG.128
// covers a contiguous 512B across the warp). inst reads should hit L2
// (populated by the reduce, protected by streaming hints). Output stores are
// streaming so they don't evict inst mid-kernel.
// ---------------------------------------------------------------------------
__global__ __launch_bounds__(256)
void iwap_scatter_kernel(const int4*  __restrict__ inst4,
                         float4* __restrict__ out4,
                         const int*   __restrict__ inst,
                         const float* __restrict__ feats,
                         float* __restrict__ out,
                         int npix) {
    __shared__ int cls[1024];

    const int t        = threadIdx.x;
    const int tileBase = blockIdx.x << 10;           // 1024 pixels per tile
    const float m0 = g_means[0], m1 = g_means[1], m2 = g_means[2];

    const int tilePix = min(1024, npix - tileBase);

    if (tilePix == 1024) {
        // Fast path: full tile.
        int4 v = __ldg(&inst4[(tileBase >> 2) + t]);
        cls[4 * t + 0] = v.x;
        cls[4 * t + 1] = v.y;
        cls[4 * t + 2] = v.z;
        cls[4 * t + 3] = v.w;
        __syncthreads();

        const int j0 = (tileBase >> 2) * 3;          // first float4 index of tile
        #pragma unroll
        for (int k = 0; k < 3; k++) {
            int   j  = j0 + (k << 8) + t;            // lane-contiguous float4
            int   f0 = 4 * ((k << 8) + t);           // float offset within tile
            float r[4];
            #pragma unroll
            for (int q = 0; q < 4; q++) {
                int local = (f0 + q) / 3;            // pixel within tile
                int c     = cls[local];
                float v2;
                if ((unsigned)c < 3u) {
                    v2 = (c == 0) ? m0 : ((c == 1) ? m1 : m2);
                } else {
                    // out-of-range class: keep original value
                    v2 = feats[(size_t)tileBase * 3 + f0 + q];
                }
                r[q] = v2;
            }
            __stcs(&out4[j], make_float4(r[0], r[1], r[2], r[3]));
        }
    } else {
        // Tail tile: scalar, bounds-checked.
        for (int p = tileBase + t; p < tileBase + tilePix; p += blockDim.x) {
            int c = inst[p];
            if ((unsigned)c < 3u) {
                float m = (c == 0) ? m0 : ((c == 1) ? m1 : m2);
                out[3 * p] = m; out[3 * p + 1] = m; out[3 * p + 2] = m;
            } else {
                out[3 * p]     = feats[3 * p];
                out[3 * p + 1] = feats[3 * p + 1];
                out[3 * p + 2] = feats[3 * p + 2];
            }
        }
    }
}

// ---------------------------------------------------------------------------
extern "C" void kernel_launch(void* const* d_in, const int* in_sizes, int n_in,
                              void* d_out, int out_size) {
    const float* feats = (const float*)d_in[0];   // [16,1024,1024,3] f32
    const int*   inst  = (const int*)d_in[1];     // [16,1024,1024,1] i32
    float*       out   = (float*)d_out;

    const int npix   = in_sizes[1];               // 16*1024*1024
    const int nitems = npix >> 2;                 // 4 pixels per reduce item

    const float4* feats4 = (const float4*)feats;
    const int4*   inst4  = (const int4*)inst;
    float4*       out4   = (float4*)out;

    iwap_zero_kernel<<<1, 32>>>();

    const int rblocks = 1216;                     // ~8 per SM, full residency
    iwap_reduce_kernel<<<rblocks, 256>>>(feats4, inst4, feats, inst, nitems, npix);

    iwap_finalize_kernel<<<1, 32>>>();

    const int sblocks = (npix + 1023) / 1024;     // one 1024-pixel tile/block
    iwap_scatter_kernel<<<sblocks, 256>>>(inst4, out4, inst, feats, out, npix);
}

// round 3
// speedup vs baseline: 1.1259x; 1.0010x over previous
#include <cuda_runtime.h>
#include <cuda_bf16.h>

// Scratch (no allocation allowed).
__device__ double             g_sums[3];
__device__ unsigned long long g_cnts[3];
__device__ float              g_means[3];

// ---------------------------------------------------------------------------
// Kernel 0: zero accumulators (graph replays reuse them).
// ---------------------------------------------------------------------------
__global__ void iwap_zero_kernel() {
    int i = threadIdx.x;
    if (i < 3) {
        g_sums[i]  = 0.0;
        g_cnts[i]  = 0ull;
        g_means[i] = 0.0f;
    }
}

// ---------------------------------------------------------------------------
// Kernel 1: grid-stride reduction. 4 pixels per item = 1 int4 + 3 float4.
// Only class 0/1 accumulated explicitly; class 2 derived from totals
// (classes partition all pixels). feats streamed (evict-first) so inst
// lines survive in L2 for the scatter.
// ---------------------------------------------------------------------------
__global__ __launch_bounds__(256)
void iwap_reduce_kernel(const float4* __restrict__ feats4,
                        const int4*  __restrict__ inst4,
                        const float* __restrict__ feats,
                        const int*   __restrict__ inst,
                        int nitems, int npix) {
    float    ptot = 0.f, s0 = 0.f, s1 = 0.f;
    unsigned c0 = 0, c1 = 0, nit = 0;

    const int stride = gridDim.x * blockDim.x;
    for (int i = blockIdx.x * blockDim.x + threadIdx.x; i < nitems; i += stride) {
        int4   cls = __ldg(&inst4[i]);
        float4 a   = __ldcs(&feats4[3 * i + 0]);
        float4 b   = __ldcs(&feats4[3 * i + 1]);
        float4 d   = __ldcs(&feats4[3 * i + 2]);
        float p0 = a.x + a.y + a.z;
        float p1 = a.w + b.x + b.y;
        float p2 = b.z + b.w + d.x;
        float p3 = d.y + d.z + d.w;
        ptot += (p0 + p1) + (p2 + p3);
        // predicated accumulate for classes 0 and 1 only
        s0 += (cls.x == 0) ? p0 : 0.f;  c0 += (cls.x == 0);
        s1 += (cls.x == 1) ? p0 : 0.f;  c1 += (cls.x == 1);
        s0 += (cls.y == 0) ? p1 : 0.f;  c0 += (cls.y == 0);
        s1 += (cls.y == 1) ? p1 : 0.f;  c1 += (cls.y == 1);
        s0 += (cls.z == 0) ? p2 : 0.f;  c0 += (cls.z == 0);
        s1 += (cls.z == 1) ? p2 : 0.f;  c1 += (cls.z == 1);
        s0 += (cls.w == 0) ? p3 : 0.f;  c0 += (cls.w == 0);
        s1 += (cls.w == 1) ? p3 : 0.f;  c1 += (cls.w == 1);
        nit++;
    }

    // Tail pixels (npix not divisible by 4) by thread 0 of block 0.
    unsigned ntail = 0;
    if (blockIdx.x == 0 && threadIdx.x == 0) {
        for (int p = nitems * 4; p < npix; p++) {
            int   c  = inst[p];
            float ps = feats[3 * p] + feats[3 * p + 1] + feats[3 * p + 2];
            ptot += ps; ntail++;
            if      (c == 0) { s0 += ps; c0++; }
            else if (c == 1) { s1 += ps; c1++; }
        }
    }

    // Derive class 2 per-thread (partition property).
    float    s2 = ptot - s0 - s1;
    unsigned c2 = 4u * nit + ntail - c0 - c1;

    #pragma unroll
    for (int off = 16; off > 0; off >>= 1) {
        s0 += __shfl_down_sync(0xffffffffu, s0, off);
        s1 += __shfl_down_sync(0xffffffffu, s1, off);
        s2 += __shfl_down_sync(0xffffffffu, s2, off);
        c0 += __shfl_down_sync(0xffffffffu, c0, off);
        c1 += __shfl_down_sync(0xffffffffu, c1, off);
        c2 += __shfl_down_sync(0xffffffffu, c2, off);
    }

    __shared__ float    bs[3];
    __shared__ unsigned bc[3];
    if (threadIdx.x < 3) { bs[threadIdx.x] = 0.f; bc[threadIdx.x] = 0u; }
    __syncthreads();
    if ((threadIdx.x & 31) == 0) {
        atomicAdd(&bs[0], s0); atomicAdd(&bs[1], s1); atomicAdd(&bs[2], s2);
        atomicAdd(&bc[0], c0); atomicAdd(&bc[1], c1); atomicAdd(&bc[2], c2);
    }
    __syncthreads();
    if (threadIdx.x < 3) {
        atomicAdd(&g_sums[threadIdx.x], (double)bs[threadIdx.x]);
        atomicAdd(&g_cnts[threadIdx.x], (unsigned long long)bc[threadIdx.x]);
    }
}

// ---------------------------------------------------------------------------
// Kernel 2: finalize means. Count includes the 3 channels (x3).
// ---------------------------------------------------------------------------
__global__ void iwap_finalize_kernel() {
    int c = threadIdx.x;
    if (c < 3) {
        double cnt = 3.0 * (double)g_cnts[c];
        g_means[c] = (cnt > 0.0) ? (float)(g_sums[c] / cnt) : 0.0f;
    }
}

// ---------------------------------------------------------------------------
// Kernel 3: scatter. Stage per-pixel MEANS in smem (class resolved once at
// staging). Each output float4 at float offset f0=4*idx spans exactly pixels
// f0/3 and f0/3+1; the split pattern depends only on idx%3:
//   mod 0 -> [lo,lo,lo,hi]   mod 1 -> [lo,lo,hi,hi]   mod 2 -> [lo,hi,hi,hi]
// Inner loop: 1 const-div, 2 LDS, 2 selects, 1 STG.128 per 16B.
// ---------------------------------------------------------------------------
__global__ __launch_bounds__(256)
void iwap_scatter_kernel(const int4*  __restrict__ inst4,
                         float4* __restrict__ out4,
                         const int*   __restrict__ inst,
                         const float* __restrict__ feats,
                         float* __restrict__ out,
                         int npix) {
    __shared__ float vmean[1024];
    __shared__ int   s_bad;

    const int t        = threadIdx.x;
    const int tileBase = blockIdx.x << 10;           // 1024 pixels per tile
    const float m0 = g_means[0], m1 = g_means[1], m2 = g_means[2];

    const int tilePix = min(1024, npix - tileBase);

    if (tilePix == 1024) {
        if (t == 0) s_bad = 0;
        __syncthreads();

        int4 v = __ldg(&inst4[(tileBase >> 2) + t]);
        bool ok = ((unsigned)v.x < 3u) & ((unsigned)v.y < 3u) &
                  ((unsigned)v.z < 3u) & ((unsigned)v.w < 3u);
        if (!ok) s_bad = 1;
        float4 mv;
        mv.x = (v.x == 0) ? m0 : ((v.x == 1) ? m1 : m2);
        mv.y = (v.y == 0) ? m0 : ((v.y == 1) ? m1 : m2);
        mv.z = (v.z == 0) ? m0 : ((v.z == 1) ? m1 : m2);
        mv.w = (v.w == 0) ? m0 : ((v.w == 1) ? m1 : m2);
        *(float4*)&vmean[4 * t] = mv;
        __syncthreads();

        const int j0   = (tileBase >> 2) * 3;        // first float4 index of tile
        const int tmod = t % 3;                      // (k*256 + t) % 3 == (k + tmod) % 3
        #pragma unroll
        for (int k = 0; k < 3; k++) {
            int   idx  = (k << 8) + t;               // float4 index within tile
            int   plo  = (4 * idx) / 3;              // low pixel of this vector
            int   mod  = tmod + k;  mod -= (mod >= 3) ? 3 : 0;
            float lo   = vmean[plo];
            float hi   = vmean[plo + 1];             // plo <= 1022, always valid
            float4 r;
            r.x = lo;
            r.y = (mod == 2) ? hi : lo;
            r.z = (mod == 0) ? lo : hi;
            r.w = hi;
            __stcs(&out4[j0 + idx], r);
        }

        // Extremely unlikely path: some class out of range -> restore feats.
        if (s_bad) {
            __syncthreads();
            for (int q = 0; q < 4; q++) {
                int p = tileBase + 4 * t + q;
                int c = __ldg(&inst[p]);
                if ((unsigned)c >= 3u) {
                    out[3 * p]     = feats[3 * p];
                    out[3 * p + 1] = feats[3 * p + 1];
                    out[3 * p + 2] = feats[3 * p + 2];
                }
            }
        }
    } else {
        // Tail tile: scalar, bounds-checked.
        for (int p = tileBase + t; p < tileBase + tilePix; p += blockDim.x) {
            int c = inst[p];
            if ((unsigned)c < 3u) {
                float m = (c == 0) ? m0 : ((c == 1) ? m1 : m2);
                out[3 * p] = m; out[3 * p + 1] = m; out[3 * p + 2] = m;
            } else {
                out[3 * p]     = feats[3 * p];
                out[3 * p + 1] = feats[3 * p + 1];
                out[3 * p + 2] = feats[3 * p + 2];
            }
        }
    }
}

// ---------------------------------------------------------------------------
extern "C" void kernel_launch(void* const* d_in, const int* in_sizes, int n_in,
                              void* d_out, int out_size) {
    const float* feats = (const float*)d_in[0];   // [16,1024,1024,3] f32
    const int*   inst  = (const int*)d_in[1];     // [16,1024,1024,1] i32
    float*       out   = (float*)d_out;

    const int npix   = in_sizes[1];               // 16*1024*1024
    const int nitems = npix >> 2;                 // 4 pixels per reduce item

    const float4* feats4 = (const float4*)feats;
    const int4*   inst4  = (const int4*)inst;
    float4*       out4   = (float4*)out;

    iwap_zero_kernel<<<1, 32>>>();

    const int rblocks = 1216;                     // 8 per SM, full residency
    iwap_reduce_kernel<<<rblocks, 256>>>(feats4, inst4, feats, inst, nitems, npix);

    iwap_finalize_kernel<<<1, 32>>>();

    const int sblocks = (npix + 1023) / 1024;     // one 1024-pixel tile/block
    iwap_scatter_kernel<<<sblocks, 256>>>(inst4, out4, inst, feats, out, npix);
}